// round 16
// baseline (speedup 1.0000x reference)
#include <cuda_runtime.h>
#include <cuda_fp16.h>
#include <cstdint>

// TCNN_INR via mma.sync fp16 m16n8k16 HMMA (fp32 accum), warp-specialized
// persistent CTAs. 512 threads: warps 0-7 MMA (mg x nw = 2x4, Mw=64/Nw=32),
// warps 8-15 encoding (2 thr/px, 6 levels, 2-level batched gathers),
// double-buffered E. ILP round: per-kt batched A loads, per-mg 128-thread
// barriers (H1f/P are mg-disjoint), enc MLP=8.

#define PRIME_Y   2654435761u
#define HASH_MASK 0xFFFFFu
#define ENC_SCALE 4096.0f
#define INV_SCALE (1.0f / 4096.0f)

__constant__ float    c_scale[12] = {15.0f, 23.0f, 35.0f, 53.0f, 80.0f, 120.5f,
                                     181.25f, 272.375f, 409.0625f, 614.09375f,
                                     921.640625f, 1382.9609375f};
__constant__ unsigned c_res[12]   = {16u, 24u, 36u, 54u, 81u, 122u,
                                     183u, 274u, 411u, 616u, 923u, 1384u};

__device__ __forceinline__ uint32_t pack_h2(float lo, float hi) {
    __half2 h = __floats2half2_rn(lo, hi);
    return *(uint32_t*)&h;
}

// half2-unit permutation within 8-unit (16 fp16) k-groups: [0,4,1,5,2,6,3,7]
__device__ __forceinline__ int uslot(int u) {
    return (u < 4) ? (u << 1) : (((u - 4) << 1) | 1);
}

__device__ __forceinline__ void mma16(float& d0, float& d1, float& d2, float& d3,
                                      uint32_t a0, uint32_t a1, uint32_t a2, uint32_t a3,
                                      uint32_t b0, uint32_t b1) {
    asm volatile("mma.sync.aligned.m16n8k16.row.col.f32.f16.f16.f32 "
                 "{%0,%1,%2,%3}, {%4,%5,%6,%7}, {%8,%9}, {%0,%1,%2,%3};"
                 : "+f"(d0), "+f"(d1), "+f"(d2), "+f"(d3)
                 : "r"(a0), "r"(a1), "r"(a2), "r"(a3), "r"(b0), "r"(b1));
}

// per-mg-group barrier: warps 0-3 (tid 0-127) use bar 2, warps 4-7 use bar 3
#define BAR_MG(mgi) asm volatile("bar.sync %0, 128;" :: "r"(2 + (mgi)) : "memory")

// SMEM uint32 offsets
#define E_STRIDE  26
#define EBUF      (128 * E_STRIDE)            // 3328
#define E_OFF     0                           // 2 buffers
#define W1F_OFF   (E_OFF   + 2 * EBUF)        // 6656   (3072 u32)
#define W2F_OFF   (W1F_OFF + 3072)            // 9728   (8192 u32)
#define H1F_OFF   (W2F_OFF + 8192)            // 17920  (8192 u32)
#define P_OFF     (H1F_OFF + 8192)            // 26112  (512 f32)
#define W3_OFF    (P_OFF   + 512)             // 26624  (128 f32)
#define SMEM_U32  (W3_OFF + 128)              // 26752
#define SMEM_BYTES (SMEM_U32 * 4)             // 107008

#define NUM_TILES 8

__global__ void __launch_bounds__(512, 1)
tcnn_hmma8_kernel(const float* __restrict__ table,
                  const float* __restrict__ w1,
                  const float* __restrict__ w2,
                  const float* __restrict__ w3,
                  float* __restrict__ out)
{
    extern __shared__ uint32_t smu[];
    uint32_t* E    = smu + E_OFF;
    uint32_t* W1f  = smu + W1F_OFF;
    uint32_t* W2f  = smu + W2F_OFF;
    uint32_t* H1f  = smu + H1F_OFF;
    float*    P    = (float*)(smu + P_OFF);    // [128 rows][4 nw]
    float*    w3s  = (float*)(smu + W3_OFF);

    const int tid  = threadIdx.x;
    const int lane = tid & 31;
    const int warp = tid >> 5;
    const int g    = lane >> 2;
    const int t    = lane & 3;
    const bool is_mma = (warp < 8);
    const int mg   = warp >> 2;      // MMA warps: M-group (0..1)
    const int nw   = warp & 3;       // MMA warps: N-slice (0..3)

    // ---- Stage weights ONCE per CTA, fp16 fragment layouts ----
    #pragma unroll
    for (int idx = tid; idx < 3072; idx += 512) {
        int pair = idx & 1;
        int ln   = (idx >> 1) & 31;
        int nt   = (idx >> 6) & 3;
        int kt   = (idx >> 8) % 3;
        int nwi  = idx / 768;
        int gg = ln >> 2, tt = ln & 3;
        int k = kt * 16 + 2 * tt + pair * 8;
        int n = nwi * 32 + nt * 8 + gg;
        W1f[idx] = pack_h2(w1[k * 128 + n], w1[(k + 1) * 128 + n]);
    }
    #pragma unroll
    for (int idx = tid; idx < 8192; idx += 512) {
        int pair = idx & 1;
        int ln   = (idx >> 1) & 31;
        int nt   = (idx >> 6) & 3;
        int kt   = (idx >> 8) & 7;
        int nwi  = idx >> 11;
        int gg = ln >> 2, tt = ln & 3;
        int k = kt * 16 + 2 * tt + pair * 8;
        int n = nwi * 32 + nt * 8 + gg;
        W2f[idx] = pack_h2(w2[k * 128 + n], w2[(k + 1) * 128 + n]);
    }
    if (tid < 128) w3s[tid] = w3[tid];
    __syncthreads();

    // ---- Encoding: enc warps (8..15), 2 thr/px, 6 levels, 2-level batches ----
    auto encode_tile = [&](int tile, uint32_t* Ebuf) {
        const int   lp    = tid & 127;
        const int   lbase = ((tid >> 7) & 1) * 6;
        const int   pix   = tile * 128 + lp;
        const float fx = (float)(pix & 1023) * (1.0f / 1023.0f);
        const float fy = (float)(pix >> 10)  * (1.0f / 1023.0f);
        uint32_t* Er = Ebuf + lp * E_STRIDE;

        #pragma unroll
        for (int lq = 0; lq < 3; lq++) {
            float4 f[2][4];
            float  wxs[2], wys[2];
            // issue all 8 gathers for both levels before using any
            #pragma unroll
            for (int s2 = 0; s2 < 2; s2++) {
                const int      l   = lbase + 2 * lq + s2;
                const float    s   = c_scale[l];
                const unsigned res = c_res[l];
                float posx = fmaf(fx, s, 0.5f);
                float posy = fmaf(fy, s, 0.5f);
                float fpx = floorf(posx), fpy = floorf(posy);
                wxs[s2] = posx - fpx;  wys[s2] = posy - fpy;
                unsigned px0 = (unsigned)fpx, py0 = (unsigned)fpy;
                unsigned px1 = min(px0 + 1u, res - 1u);
                unsigned py1 = min(py0 + 1u, res - 1u);

                unsigned i00, i10, i01, i11;
                if (l < 11) {
                    i00 = px0 + py0 * res;  i10 = px1 + py0 * res;
                    i01 = px0 + py1 * res;  i11 = px1 + py1 * res;
                } else {
                    unsigned hy0 = py0 * PRIME_Y, hy1 = py1 * PRIME_Y;
                    i00 = (px0 ^ hy0) & HASH_MASK;  i10 = (px1 ^ hy0) & HASH_MASK;
                    i01 = (px0 ^ hy1) & HASH_MASK;  i11 = (px1 ^ hy1) & HASH_MASK;
                }
                const float4* tb = (const float4*)table + ((size_t)l << 20);
                f[s2][0] = __ldg(tb + i00);
                f[s2][1] = __ldg(tb + i10);
                f[s2][2] = __ldg(tb + i01);
                f[s2][3] = __ldg(tb + i11);
            }
            #pragma unroll
            for (int s2 = 0; s2 < 2; s2++) {
                const int l = lbase + 2 * lq + s2;
                float wx = wxs[s2], wy = wys[s2];
                float w00 = (1.0f - wx) * (1.0f - wy) * ENC_SCALE;
                float w10 = wx * (1.0f - wy) * ENC_SCALE;
                float w01 = (1.0f - wx) * wy * ENC_SCALE;
                float w11 = wx * wy * ENC_SCALE;

                float e0 = f[s2][0].x*w00 + f[s2][1].x*w10 + f[s2][2].x*w01 + f[s2][3].x*w11;
                float e1 = f[s2][0].y*w00 + f[s2][1].y*w10 + f[s2][2].y*w01 + f[s2][3].y*w11;
                float e2 = f[s2][0].z*w00 + f[s2][1].z*w10 + f[s2][2].z*w01 + f[s2][3].z*w11;
                float e3 = f[s2][0].w*w00 + f[s2][1].w*w10 + f[s2][2].w*w01 + f[s2][3].w*w11;

                int grp = l >> 2;
                int u0  = (2 * l) & 7;
                Er[grp * 8 + uslot(u0)]     = pack_h2(e0, e1);
                Er[grp * 8 + uslot(u0 + 1)] = pack_h2(e2, e3);
            }
        }
    };

    // ---- Prologue ----
    if (!is_mma) encode_tile(blockIdx.x * NUM_TILES, E);
    __syncthreads();

    // ---- Tile loop ----
    #pragma unroll 1
    for (int it = 0; it < NUM_TILES; it++) {
        if (!is_mma) {
            if (it + 1 < NUM_TILES)
                encode_tile(blockIdx.x * NUM_TILES + it + 1, E + ((it + 1) & 1) * EBUF);
        } else {
            const uint32_t* Eb = E + (it & 1) * EBUF;

            // ---- Layer 1: H1[mg*64..+64, nw*32..+32), K=48 ----
            {
                uint32_t Bf[4][3][2];
                #pragma unroll
                for (int nt = 0; nt < 4; nt++)
                    #pragma unroll
                    for (int kt = 0; kt < 3; kt++) {
                        uint2 v = *(const uint2*)(W1f + (((nw * 3 + kt) * 4 + nt) * 32 + lane) * 2);
                        Bf[nt][kt][0] = v.x;  Bf[nt][kt][1] = v.y;
                    }

                float d[4][4][4];
                #pragma unroll
                for (int mi = 0; mi < 4; mi++)
                    #pragma unroll
                    for (int nt = 0; nt < 4; nt++)
                        d[mi][nt][0] = d[mi][nt][1] = d[mi][nt][2] = d[mi][nt][3] = 0.0f;

                #pragma unroll
                for (int kt = 0; kt < 3; kt++) {
                    // batch all 4 mi A-fragment loads, then the 16 MMAs
                    uint2 ua[4], ub[4];
                    #pragma unroll
                    for (int mi = 0; mi < 4; mi++) {
                        int mt = mg * 4 + mi;
                        ua[mi] = *(const uint2*)(Eb + (mt*16 + g    ) * E_STRIDE + kt * 8 + 2 * t);
                        ub[mi] = *(const uint2*)(Eb + (mt*16 + g + 8) * E_STRIDE + kt * 8 + 2 * t);
                    }
                    #pragma unroll
                    for (int mi = 0; mi < 4; mi++)
                        #pragma unroll
                        for (int nt = 0; nt < 4; nt++)
                            mma16(d[mi][nt][0], d[mi][nt][1], d[mi][nt][2], d[mi][nt][3],
                                  ua[mi].x, ub[mi].x, ua[mi].y, ub[mi].y,
                                  Bf[nt][kt][0], Bf[nt][kt][1]);
                }

                // ReLU -> fp16 -> H1f (fragment-native, mg-disjoint rows)
                #pragma unroll
                for (int mi = 0; mi < 4; mi++) {
                    #pragma unroll
                    for (int j = 0; j < 2; j++) {
                        int mt  = mg * 4 + mi;
                        int ktc = nw * 2 + j;
                        uint4 v;
                        v.x = pack_h2(fmaxf(d[mi][2*j  ][0], 0.0f), fmaxf(d[mi][2*j  ][1], 0.0f));
                        v.y = pack_h2(fmaxf(d[mi][2*j  ][2], 0.0f), fmaxf(d[mi][2*j  ][3], 0.0f));
                        v.z = pack_h2(fmaxf(d[mi][2*j+1][0], 0.0f), fmaxf(d[mi][2*j+1][1], 0.0f));
                        v.w = pack_h2(fmaxf(d[mi][2*j+1][2], 0.0f), fmaxf(d[mi][2*j+1][3], 0.0f));
                        *(uint4*)(H1f + ((mt * 8 + ktc) * 32 + lane) * 4) = v;
                    }
                }
            }
            BAR_MG(mg);

            // ---- Layer 2 (+w3): H2[mg*64..+64, nw*32..+32), K=128 ----
            {
                float d[4][4][4];
                #pragma unroll
                for (int mi = 0; mi < 4; mi++)
                    #pragma unroll
                    for (int nt = 0; nt < 4; nt++)
                        d[mi][nt][0] = d[mi][nt][1] = d[mi][nt][2] = d[mi][nt][3] = 0.0f;

                #pragma unroll
                for (int kc = 0; kc < 2; kc++) {
                    uint32_t Bf[4][4][2];
                    #pragma unroll
                    for (int nt = 0; nt < 4; nt++)
                        #pragma unroll
                        for (int kq = 0; kq < 4; kq++) {
                            int kt = kc * 4 + kq;
                            uint2 v = *(const uint2*)(W2f + (((nw * 8 + kt) * 4 + nt) * 32 + lane) * 2);
                            Bf[nt][kq][0] = v.x;  Bf[nt][kq][1] = v.y;
                        }
                    #pragma unroll
                    for (int kq = 0; kq < 4; kq++) {
                        int kt = kc * 4 + kq;
                        // batch all 4 mi A loads, then the 16 MMAs
                        uint4 A4[4];
                        #pragma unroll
                        for (int mi = 0; mi < 4; mi++) {
                            int mt = mg * 4 + mi;
                            A4[mi] = *(const uint4*)(H1f + ((mt * 8 + kt) * 32 + lane) * 4);
                        }
                        #pragma unroll
                        for (int mi = 0; mi < 4; mi++)
                            #pragma unroll
                            for (int nt = 0; nt < 4; nt++)
                                mma16(d[mi][nt][0], d[mi][nt][1], d[mi][nt][2], d[mi][nt][3],
                                      A4[mi].x, A4[mi].y, A4[mi].z, A4[mi].w,
                                      Bf[nt][kq][0], Bf[nt][kq][1]);
                    }
                }

                // Layer 3 partials over this warp's 32 cols
                float w3c[4][2];
                #pragma unroll
                for (int nt = 0; nt < 4; nt++) {
                    w3c[nt][0] = w3s[nw * 32 + nt * 8 + 2 * t];
                    w3c[nt][1] = w3s[nw * 32 + nt * 8 + 2 * t + 1];
                }
                #pragma unroll
                for (int mi = 0; mi < 4; mi++) {
                    float p0 = 0.0f, p1 = 0.0f;
                    #pragma unroll
                    for (int nt = 0; nt < 4; nt++) {
                        p0 += fmaxf(d[mi][nt][0], 0.0f) * w3c[nt][0]
                            + fmaxf(d[mi][nt][1], 0.0f) * w3c[nt][1];
                        p1 += fmaxf(d[mi][nt][2], 0.0f) * w3c[nt][0]
                            + fmaxf(d[mi][nt][3], 0.0f) * w3c[nt][1];
                    }
                    p0 += __shfl_xor_sync(0xFFFFFFFFu, p0, 1);
                    p0 += __shfl_xor_sync(0xFFFFFFFFu, p0, 2);
                    p1 += __shfl_xor_sync(0xFFFFFFFFu, p1, 1);
                    p1 += __shfl_xor_sync(0xFFFFFFFFu, p1, 2);
                    if (t == 0) {
                        int row0 = mg * 64 + mi * 16 + g;
                        P[(row0    ) * 4 + nw] = p0;
                        P[(row0 + 8) * 4 + nw] = p1;
                    }
                }
            }
            BAR_MG(mg);

            // ---- Per-mg reduction + output (rows mg*64..+64) ----
            {
                int ltid = tid - mg * 128;
                if (ltid < 64) {
                    int row = mg * 64 + ltid;
                    float4 v = *(const float4*)(P + row * 4);
                    out[(blockIdx.x * NUM_TILES + it) * 128 + row] =
                        (v.x + v.y + v.z + v.w) * INV_SCALE;
                }
            }
        }
        __syncthreads();   // E buffer handoff (enc <-> MMA)
    }
}

extern "C" void kernel_launch(void* const* d_in, const int* in_sizes, int n_in,
                              void* d_out, int out_size)
{
    const float *table = nullptr, *w1 = nullptr, *w2 = nullptr, *w3 = nullptr;
    for (int i = 0; i < n_in; i++) {
        switch (in_sizes[i]) {
            case 50331648: table = (const float*)d_in[i]; break;
            case 6144:     w1    = (const float*)d_in[i]; break;
            case 16384:    w2    = (const float*)d_in[i]; break;
            case 128:      w3    = (const float*)d_in[i]; break;
            default: break;
        }
    }
    cudaFuncSetAttribute(tcnn_hmma8_kernel,
                         cudaFuncAttributeMaxDynamicSharedMemorySize, SMEM_BYTES);
    tcnn_hmma8_kernel<<<1024, 512, SMEM_BYTES>>>(table, w1, w2, w3, (float*)d_out);
}

// round 17
// speedup vs baseline: 1.0542x; 1.0542x over previous
#include <cuda_runtime.h>
#include <cuda_fp16.h>
#include <cstdint>

// TCNN_INR via mma.sync fp16 m16n8k16 HMMA (fp32 accum), warp-specialized
// persistent CTAs with DECOUPLED producer/consumer pipeline.
// 512 threads: warps 0-7 MMA (mg x nw = 2x4, Mw=64/Nw=32), warps 8-15 enc
// (2 thr/px, 6 levels). E double-buffered; handoff via named-barrier
// arrive/wait pairs (full0/full1/empty0/empty1) instead of __syncthreads,
// so enc runs up to 2 tiles ahead. MMA inner loops identical to the R14
// 189us schedule. Encoding scaled by 2^12 for fp16 range; undone at output.

#define PRIME_Y   2654435761u
#define HASH_MASK 0xFFFFFu
#define ENC_SCALE 4096.0f
#define INV_SCALE (1.0f / 4096.0f)

__constant__ float    c_scale[12] = {15.0f, 23.0f, 35.0f, 53.0f, 80.0f, 120.5f,
                                     181.25f, 272.375f, 409.0625f, 614.09375f,
                                     921.640625f, 1382.9609375f};
__constant__ unsigned c_res[12]   = {16u, 24u, 36u, 54u, 81u, 122u,
                                     183u, 274u, 411u, 616u, 923u, 1384u};

__device__ __forceinline__ uint32_t pack_h2(float lo, float hi) {
    __half2 h = __floats2half2_rn(lo, hi);
    return *(uint32_t*)&h;
}

// half2-unit permutation within 8-unit (16 fp16) k-groups: [0,4,1,5,2,6,3,7]
__device__ __forceinline__ int uslot(int u) {
    return (u < 4) ? (u << 1) : (((u - 4) << 1) | 1);
}

__device__ __forceinline__ void mma16(float& d0, float& d1, float& d2, float& d3,
                                      uint32_t a0, uint32_t a1, uint32_t a2, uint32_t a3,
                                      uint32_t b0, uint32_t b1) {
    asm volatile("mma.sync.aligned.m16n8k16.row.col.f32.f16.f16.f32 "
                 "{%0,%1,%2,%3}, {%4,%5,%6,%7}, {%8,%9}, {%0,%1,%2,%3};"
                 : "+f"(d0), "+f"(d1), "+f"(d2), "+f"(d3)
                 : "r"(a0), "r"(a1), "r"(a2), "r"(a3), "r"(b0), "r"(b1));
}

// barrier 1: MMA-warps-only internal sync (256 threads)
#define BAR_MMA() asm volatile("bar.sync 1, 256;" ::: "memory")
// producer/consumer handoff barriers (512 expected arrivals each):
// full[b] = E buffer b filled;  empty[b] = E buffer b free for refill
#define FULL_WAIT(b)    asm volatile("bar.sync %0, 512;"   :: "r"(4 + (b)) : "memory")
#define FULL_ARRIVE(b)  asm volatile("bar.arrive %0, 512;" :: "r"(4 + (b)) : "memory")
#define EMPTY_WAIT(b)   asm volatile("bar.sync %0, 512;"   :: "r"(6 + (b)) : "memory")
#define EMPTY_ARRIVE(b) asm volatile("bar.arrive %0, 512;" :: "r"(6 + (b)) : "memory")

// SMEM uint32 offsets
#define E_STRIDE  26
#define EBUF      (128 * E_STRIDE)            // 3328
#define E_OFF     0                           // 2 buffers
#define W1F_OFF   (E_OFF   + 2 * EBUF)        // 6656   (3072 u32)
#define W2F_OFF   (W1F_OFF + 3072)            // 9728   (8192 u32)
#define H1F_OFF   (W2F_OFF + 8192)            // 17920  (8192 u32)
#define P_OFF     (H1F_OFF + 8192)            // 26112  (512 f32)
#define W3_OFF    (P_OFF   + 512)             // 26624  (128 f32)
#define SMEM_U32  (W3_OFF + 128)              // 26752
#define SMEM_BYTES (SMEM_U32 * 4)             // 107008

#define NUM_TILES 8

__global__ void __launch_bounds__(512, 1)
tcnn_hmma9_kernel(const float* __restrict__ table,
                  const float* __restrict__ w1,
                  const float* __restrict__ w2,
                  const float* __restrict__ w3,
                  float* __restrict__ out)
{
    extern __shared__ uint32_t smu[];
    uint32_t* E    = smu + E_OFF;
    uint32_t* W1f  = smu + W1F_OFF;
    uint32_t* W2f  = smu + W2F_OFF;
    uint32_t* H1f  = smu + H1F_OFF;
    float*    P    = (float*)(smu + P_OFF);    // [128 rows][4 nw]
    float*    w3s  = (float*)(smu + W3_OFF);

    const int tid  = threadIdx.x;
    const int lane = tid & 31;
    const int warp = tid >> 5;
    const int g    = lane >> 2;
    const int t    = lane & 3;
    const bool is_mma = (warp < 8);
    const int mg   = warp >> 2;      // MMA warps: M-group (0..1)
    const int nw   = warp & 3;       // MMA warps: N-slice (0..3)

    // ---- Stage weights ONCE per CTA, fp16 fragment layouts ----
    #pragma unroll
    for (int idx = tid; idx < 3072; idx += 512) {
        int pair = idx & 1;
        int ln   = (idx >> 1) & 31;
        int nt   = (idx >> 6) & 3;
        int kt   = (idx >> 8) % 3;
        int nwi  = idx / 768;
        int gg = ln >> 2, tt = ln & 3;
        int k = kt * 16 + 2 * tt + pair * 8;
        int n = nwi * 32 + nt * 8 + gg;
        W1f[idx] = pack_h2(w1[k * 128 + n], w1[(k + 1) * 128 + n]);
    }
    #pragma unroll
    for (int idx = tid; idx < 8192; idx += 512) {
        int pair = idx & 1;
        int ln   = (idx >> 1) & 31;
        int nt   = (idx >> 6) & 3;
        int kt   = (idx >> 8) & 7;
        int nwi  = idx >> 11;
        int gg = ln >> 2, tt = ln & 3;
        int k = kt * 16 + 2 * tt + pair * 8;
        int n = nwi * 32 + nt * 8 + gg;
        W2f[idx] = pack_h2(w2[k * 128 + n], w2[(k + 1) * 128 + n]);
    }
    if (tid < 128) w3s[tid] = w3[tid];
    __syncthreads();

    if (!is_mma) {
        // ================= Encoding warps (8..15) =================
        const int   lp    = tid & 127;
        const int   lbase = ((tid >> 7) & 1) * 6;

        #pragma unroll 1
        for (int j = 0; j < NUM_TILES; j++) {
            if (j >= 2) EMPTY_WAIT(j & 1);

            const int   pix = (blockIdx.x * NUM_TILES + j) * 128 + lp;
            const float fx = (float)(pix & 1023) * (1.0f / 1023.0f);
            const float fy = (float)(pix >> 10)  * (1.0f / 1023.0f);
            uint32_t* Er = E + (j & 1) * EBUF + lp * E_STRIDE;

            #pragma unroll
            for (int li = 0; li < 6; li++) {
                const int      l   = lbase + li;
                const float    s   = c_scale[l];
                const unsigned res = c_res[l];
                float posx = fmaf(fx, s, 0.5f);
                float posy = fmaf(fy, s, 0.5f);
                float fpx = floorf(posx), fpy = floorf(posy);
                float wx = posx - fpx,    wy = posy - fpy;
                unsigned px0 = (unsigned)fpx, py0 = (unsigned)fpy;
                unsigned px1 = min(px0 + 1u, res - 1u);
                unsigned py1 = min(py0 + 1u, res - 1u);

                unsigned i00, i10, i01, i11;
                if (l < 11) {
                    i00 = px0 + py0 * res;  i10 = px1 + py0 * res;
                    i01 = px0 + py1 * res;  i11 = px1 + py1 * res;
                } else {
                    unsigned hy0 = py0 * PRIME_Y, hy1 = py1 * PRIME_Y;
                    i00 = (px0 ^ hy0) & HASH_MASK;  i10 = (px1 ^ hy0) & HASH_MASK;
                    i01 = (px0 ^ hy1) & HASH_MASK;  i11 = (px1 ^ hy1) & HASH_MASK;
                }

                const float4* tb = (const float4*)table + ((size_t)l << 20);
                float4 f00 = __ldg(tb + i00);
                float4 f10 = __ldg(tb + i10);
                float4 f01 = __ldg(tb + i01);
                float4 f11 = __ldg(tb + i11);

                float w00 = (1.0f - wx) * (1.0f - wy) * ENC_SCALE;
                float w10 = wx * (1.0f - wy) * ENC_SCALE;
                float w01 = (1.0f - wx) * wy * ENC_SCALE;
                float w11 = wx * wy * ENC_SCALE;

                float e0 = f00.x*w00 + f10.x*w10 + f01.x*w01 + f11.x*w11;
                float e1 = f00.y*w00 + f10.y*w10 + f01.y*w01 + f11.y*w11;
                float e2 = f00.z*w00 + f10.z*w10 + f01.z*w01 + f11.z*w11;
                float e3 = f00.w*w00 + f10.w*w10 + f01.w*w01 + f11.w*w11;

                int grp = l >> 2;
                int u0  = (2 * l) & 7;
                Er[grp * 8 + uslot(u0)]     = pack_h2(e0, e1);
                Er[grp * 8 + uslot(u0 + 1)] = pack_h2(e2, e3);
            }

            FULL_ARRIVE(j & 1);
        }
    } else {
        // ================= MMA warps (0..7) =================
        #pragma unroll 1
        for (int it = 0; it < NUM_TILES; it++) {
            FULL_WAIT(it & 1);
            const uint32_t* Eb = E + (it & 1) * EBUF;

            // ---- Layer 1: H1[mg*64..+64, nw*32..+32), K=48 ----
            {
                uint32_t Bf[4][3][2];
                #pragma unroll
                for (int nt = 0; nt < 4; nt++)
                    #pragma unroll
                    for (int kt = 0; kt < 3; kt++) {
                        uint2 v = *(const uint2*)(W1f + (((nw * 3 + kt) * 4 + nt) * 32 + lane) * 2);
                        Bf[nt][kt][0] = v.x;  Bf[nt][kt][1] = v.y;
                    }

                float d[4][4][4];
                #pragma unroll
                for (int mi = 0; mi < 4; mi++)
                    #pragma unroll
                    for (int nt = 0; nt < 4; nt++)
                        d[mi][nt][0] = d[mi][nt][1] = d[mi][nt][2] = d[mi][nt][3] = 0.0f;

                #pragma unroll
                for (int kt = 0; kt < 3; kt++) {
                    #pragma unroll
                    for (int mi = 0; mi < 4; mi++) {
                        int mt = mg * 4 + mi;
                        uint2 ua = *(const uint2*)(Eb + (mt*16 + g    ) * E_STRIDE + kt * 8 + 2 * t);
                        uint2 ub = *(const uint2*)(Eb + (mt*16 + g + 8) * E_STRIDE + kt * 8 + 2 * t);
                        #pragma unroll
                        for (int nt = 0; nt < 4; nt++)
                            mma16(d[mi][nt][0], d[mi][nt][1], d[mi][nt][2], d[mi][nt][3],
                                  ua.x, ub.x, ua.y, ub.y, Bf[nt][kt][0], Bf[nt][kt][1]);
                    }
                }

                // ReLU -> fp16 -> H1f (fragment-native)
                #pragma unroll
                for (int mi = 0; mi < 4; mi++) {
                    #pragma unroll
                    for (int j = 0; j < 2; j++) {
                        int mt  = mg * 4 + mi;
                        int ktc = nw * 2 + j;
                        uint4 v;
                        v.x = pack_h2(fmaxf(d[mi][2*j  ][0], 0.0f), fmaxf(d[mi][2*j  ][1], 0.0f));
                        v.y = pack_h2(fmaxf(d[mi][2*j  ][2], 0.0f), fmaxf(d[mi][2*j  ][3], 0.0f));
                        v.z = pack_h2(fmaxf(d[mi][2*j+1][0], 0.0f), fmaxf(d[mi][2*j+1][1], 0.0f));
                        v.w = pack_h2(fmaxf(d[mi][2*j+1][2], 0.0f), fmaxf(d[mi][2*j+1][3], 0.0f));
                        *(uint4*)(H1f + ((mt * 8 + ktc) * 32 + lane) * 4) = v;
                    }
                }
            }
            BAR_MMA();

            // ---- Layer 2 (+w3): H2[mg*64..+64, nw*32..+32), K=128 ----
            {
                float d[4][4][4];
                #pragma unroll
                for (int mi = 0; mi < 4; mi++)
                    #pragma unroll
                    for (int nt = 0; nt < 4; nt++)
                        d[mi][nt][0] = d[mi][nt][1] = d[mi][nt][2] = d[mi][nt][3] = 0.0f;

                #pragma unroll
                for (int kc = 0; kc < 2; kc++) {
                    uint32_t Bf[4][4][2];
                    #pragma unroll
                    for (int nt = 0; nt < 4; nt++)
                        #pragma unroll
                        for (int kq = 0; kq < 4; kq++) {
                            int kt = kc * 4 + kq;
                            uint2 v = *(const uint2*)(W2f + (((nw * 8 + kt) * 4 + nt) * 32 + lane) * 2);
                            Bf[nt][kq][0] = v.x;  Bf[nt][kq][1] = v.y;
                        }
                    #pragma unroll
                    for (int kq = 0; kq < 4; kq++) {
                        int kt = kc * 4 + kq;
                        #pragma unroll
                        for (int mi = 0; mi < 4; mi++) {
                            int mt = mg * 4 + mi;
                            uint4 A = *(const uint4*)(H1f + ((mt * 8 + kt) * 32 + lane) * 4);
                            #pragma unroll
                            for (int nt = 0; nt < 4; nt++)
                                mma16(d[mi][nt][0], d[mi][nt][1], d[mi][nt][2], d[mi][nt][3],
                                      A.x, A.y, A.z, A.w, Bf[nt][kq][0], Bf[nt][kq][1]);
                        }
                    }
                }

                // Layer 3 partials over this warp's 32 cols
                float w3c[4][2];
                #pragma unroll
                for (int nt = 0; nt < 4; nt++) {
                    w3c[nt][0] = w3s[nw * 32 + nt * 8 + 2 * t];
                    w3c[nt][1] = w3s[nw * 32 + nt * 8 + 2 * t + 1];
                }
                #pragma unroll
                for (int mi = 0; mi < 4; mi++) {
                    float p0 = 0.0f, p1 = 0.0f;
                    #pragma unroll
                    for (int nt = 0; nt < 4; nt++) {
                        p0 += fmaxf(d[mi][nt][0], 0.0f) * w3c[nt][0]
                            + fmaxf(d[mi][nt][1], 0.0f) * w3c[nt][1];
                        p1 += fmaxf(d[mi][nt][2], 0.0f) * w3c[nt][0]
                            + fmaxf(d[mi][nt][3], 0.0f) * w3c[nt][1];
                    }
                    p0 += __shfl_xor_sync(0xFFFFFFFFu, p0, 1);
                    p0 += __shfl_xor_sync(0xFFFFFFFFu, p0, 2);
                    p1 += __shfl_xor_sync(0xFFFFFFFFu, p1, 1);
                    p1 += __shfl_xor_sync(0xFFFFFFFFu, p1, 2);
                    if (t == 0) {
                        int row0 = mg * 64 + mi * 16 + g;
                        P[(row0    ) * 4 + nw] = p0;
                        P[(row0 + 8) * 4 + nw] = p1;
                    }
                }
            }
            BAR_MMA();

            // ---- Cross-warp reduction + output (E no longer needed: release) ----
            EMPTY_ARRIVE(it & 1);
            if (tid < 128) {
                float4 v = *(const float4*)(P + tid * 4);
                out[(blockIdx.x * NUM_TILES + it) * 128 + tid] =
                    (v.x + v.y + v.z + v.w) * INV_SCALE;
            }
        }
    }
}

extern "C" void kernel_launch(void* const* d_in, const int* in_sizes, int n_in,
                              void* d_out, int out_size)
{
    const float *table = nullptr, *w1 = nullptr, *w2 = nullptr, *w3 = nullptr;
    for (int i = 0; i < n_in; i++) {
        switch (in_sizes[i]) {
            case 50331648: table = (const float*)d_in[i]; break;
            case 6144:     w1    = (const float*)d_in[i]; break;
            case 16384:    w2    = (const float*)d_in[i]; break;
            case 128:      w3    = (const float*)d_in[i]; break;
            default: break;
        }
    }
    cudaFuncSetAttribute(tcnn_hmma9_kernel,
                         cudaFuncAttributeMaxDynamicSharedMemorySize, SMEM_BYTES);
    tcnn_hmma9_kernel<<<1024, 512, SMEM_BYTES>>>(table, w1, w2, w3, (float*)d_out);
}